// round 2
// baseline (speedup 1.0000x reference)
#include <cuda_runtime.h>
#include <cstdint>

#define IN_DIM   5000
#define TOPK     50
#define BATCH    16384
#define H1       32
#define H2       16
#define OUT_DIM  30

#define NBIN     4096
#define MAXCAND  1024

// scratch (no allocations allowed)
__device__ int g_topk_idx[64];

static __device__ __forceinline__ unsigned key32(float f) {
    unsigned u = __float_as_uint(f);
    return (u & 0x80000000u) ? ~u : (u | 0x80000000u);  // monotonic: larger float -> larger key
}

// ---------------------------------------------------------------------------
// Kernel 1: single-CTA histogram top-k -> mask + compact index list
// grid = 1, block = 1024
// ---------------------------------------------------------------------------
__global__ void __launch_bounds__(1024, 1)
k_topk(const float* __restrict__ logits, float* __restrict__ mask_out) {
    __shared__ unsigned skey[IN_DIM];         // 20000 B
    __shared__ int hist[NBIN];                // 16384 B
    __shared__ int groupsum[128];
    __shared__ int s_T, s_m, s_ncand;
    __shared__ int      cand_idx[MAXCAND];
    __shared__ unsigned cand_key[MAXCAND];
    __shared__ unsigned char sel[IN_DIM];

    const int tid = threadIdx.x;

    for (int i = tid; i < NBIN; i += 1024) hist[i] = 0;
    if (tid == 0) s_ncand = 0;
    __syncthreads();

    // pass 1: keys + 12-bit histogram
    for (int i = tid; i < IN_DIM; i += 1024) {
        unsigned u = key32(logits[i]);
        skey[i] = u;
        atomicAdd(&hist[u >> 20], 1);
    }
    __syncthreads();

    // suffix scan (descending bins) to find threshold bin
    if (tid < 128) {
        int s = 0;
#pragma unroll
        for (int j = 0; j < 32; j++) s += hist[tid * 32 + j];
        groupsum[tid] = s;
    }
    __syncthreads();
    if (tid == 0) {
        int acc = 0, g = 127;
        for (; g > 0; g--) { if (acc + groupsum[g] >= TOPK) break; acc += groupsum[g]; }
        int b = g * 32 + 31;
        for (; b > g * 32; b--) { if (acc + hist[b] >= TOPK) break; acc += hist[b]; }
        s_T = b;              // threshold bin
        s_m = TOPK - acc;     // how many to take from bin T (acc = count in bins > T)
    }
    __syncthreads();
    const int T = s_T, m = s_m;

    // pass 2: classify; collect bin-T candidates
    for (int i = tid; i < IN_DIM; i += 1024) {
        const int b = (int)(skey[i] >> 20);
        sel[i] = (b > T) ? 1 : 0;
        if (b == T) {
            int c = atomicAdd(&s_ncand, 1);
            if (c < MAXCAND) { cand_idx[c] = i; cand_key[c] = skey[i]; }
        }
    }
    __syncthreads();

    // exact rank among candidates (tiny c, ~30 expected); tie -> lower index wins
    const int nc = min(s_ncand, MAXCAND);
    for (int ci = tid; ci < nc; ci += 1024) {
        const unsigned ki = cand_key[ci];
        const int      ii = cand_idx[ci];
        int rank = 0;
        for (int cj = 0; cj < nc; cj++) {
            const unsigned kj = cand_key[cj];
            rank += (kj > ki || (kj == ki && cand_idx[cj] < ii)) ? 1 : 0;
        }
        if (rank < m) sel[ii] = 1;
    }
    __syncthreads();

    // outputs: mask + deterministic index-ordered compaction (warp 0)
    if (mask_out)
        for (int i = tid; i < IN_DIM; i += 1024)
            mask_out[i] = sel[i] ? 1.0f : 0.0f;

    if (tid < 32) {
        int base = 0;
        for (int c0 = 0; c0 < IN_DIM; c0 += 32) {
            const int i = c0 + tid;
            const bool s = (i < IN_DIM) && sel[i];
            const unsigned b = __ballot_sync(0xffffffffu, s);
            if (s) g_topk_idx[base + __popc(b & ((1u << tid) - 1u))] = i;
            base += __popc(b);
        }
    }
}

// ---------------------------------------------------------------------------
// Kernel 2: fused gather + 3-layer MLP. Thread pair per row:
//   half = tid&1 computes 16 of 32 layer-1 outputs; exchange via shfl_xor(1);
//   layers 2/3 computed redundantly (tiny); output stores split 15/15.
// grid = 256, block = 128  (64 rows per block)
// ---------------------------------------------------------------------------
__global__ void __launch_bounds__(128, 1)
k_mlp(const float* __restrict__ x,
      const float* __restrict__ W1, const float* __restrict__ b1,
      const float* __restrict__ W2, const float* __restrict__ b2,
      const float* __restrict__ W3, const float* __restrict__ b3,
      float* __restrict__ out) {
    __shared__ int   sidx[TOPK];
    __shared__ float sW1[TOPK][H1];
    __shared__ float sW2[H1][H2];
    __shared__ float sW3[H2][OUT_DIM];
    __shared__ float sb1[H1], sb2[H2], sb3[OUT_DIM];

    const int tid = threadIdx.x;
    if (tid < TOPK)    sidx[tid] = g_topk_idx[tid];
    if (tid < H1)      sb1[tid] = b1[tid];
    if (tid < H2)      sb2[tid] = b2[tid];
    if (tid < OUT_DIM) sb3[tid] = b3[tid];
    __syncthreads();

    for (int t = tid; t < TOPK * H1; t += blockDim.x) {
        const int k = t >> 5, j = t & 31;
        sW1[k][j] = W1[(long)sidx[k] * H1 + j];
    }
    for (int t = tid; t < H1 * H2; t += blockDim.x)
        sW2[t / H2][t % H2] = W2[t];
    for (int t = tid; t < H2 * OUT_DIM; t += blockDim.x)
        sW3[t / OUT_DIM][t % OUT_DIM] = W3[t];
    __syncthreads();

    const int row  = blockIdx.x * 64 + (tid >> 1);
    const int half = tid & 1;
    if (row >= BATCH) return;
    const float* __restrict__ xr = x + (long)row * IN_DIM;

    // gather all 50 inputs (pair lanes hit identical addresses -> coalesced)
    float xv[TOPK];
#pragma unroll
    for (int k = 0; k < TOPK; k++)
        xv[k] = __ldg(xr + sidx[k]);

    // layer 1: this thread computes 16 outputs j in [half*16, half*16+16)
    const int jb = half * 16;
    float a1h[16];
#pragma unroll
    for (int p = 0; p < 16; p++) a1h[p] = sb1[jb + p];
#pragma unroll
    for (int k = 0; k < TOPK; k++) {
        const float v = xv[k];
#pragma unroll
        for (int p = 0; p < 16; p++)
            a1h[p] = fmaf(v, sW1[k][jb + p], a1h[p]);
    }

    // exchange halves with pair thread, build full relu(a1)[32]
    float a1[H1];
#pragma unroll
    for (int p = 0; p < 16; p++) {
        const float mine = a1h[p];
        const float oth  = __shfl_xor_sync(0xffffffffu, mine, 1);
        if (half == 0) { a1[p] = mine; a1[16 + p] = oth; }
        else           { a1[p] = oth;  a1[16 + p] = mine; }
    }
#pragma unroll
    for (int j = 0; j < H1; j++) a1[j] = fmaxf(a1[j], 0.0f);

    // layer 2 (redundant per pair, small)
    float a2[H2];
#pragma unroll
    for (int j = 0; j < H2; j++) a2[j] = sb2[j];
#pragma unroll
    for (int i = 0; i < H1; i++) {
        const float v = a1[i];
#pragma unroll
        for (int j = 0; j < H2; j++)
            a2[j] = fmaf(v, sW2[i][j], a2[j]);
    }
#pragma unroll
    for (int j = 0; j < H2; j++) a2[j] = fmaxf(a2[j], 0.0f);

    // layer 3: each thread writes its 15 outputs
    float* __restrict__ orow = out + (long)row * OUT_DIM + half * 15;
#pragma unroll
    for (int jj = 0; jj < 15; jj++) {
        const int j = half * 15 + jj;
        float s = sb3[j];
#pragma unroll
        for (int i = 0; i < H2; i++)
            s = fmaf(a2[i], sW3[i][j], s);
        orow[jj] = s;
    }
}

// ---------------------------------------------------------------------------
extern "C" void kernel_launch(void* const* d_in, const int* in_sizes, int n_in,
                              void* d_out, int out_size) {
    const float* x      = (const float*)d_in[0];
    const float* logits = (const float*)d_in[1];
    const float* W1     = (const float*)d_in[2];
    const float* b1     = (const float*)d_in[3];
    const float* W2     = (const float*)d_in[4];
    const float* b2     = (const float*)d_in[5];
    const float* W3     = (const float*)d_in[6];
    const float* b3     = (const float*)d_in[7];

    float* out  = (float*)d_out;
    float* mask = nullptr;
    if (out_size >= BATCH * OUT_DIM + IN_DIM)
        mask = out + (long)BATCH * OUT_DIM;   // tuple order: (out, mask)

    k_topk<<<1, 1024>>>(logits, mask);
    k_mlp <<<256, 128>>>(x, W1, b1, W2, b2, W3, b3, out);
}

// round 3
// speedup vs baseline: 1.0611x; 1.0611x over previous
#include <cuda_runtime.h>
#include <cstdint>

#define IN_DIM   5000
#define TOPK     50
#define TOPK_PAD 52      // 4 quarters * 13
#define BATCH    16384
#define H1       32
#define H1P      33      // padded row stride (bank-conflict-free for quad access)
#define H2       16
#define OUT_DIM  30

#define NBIN     4096
#define MAXCAND  1024

// scratch (no allocations allowed)
__device__ int g_topk_idx[64];

static __device__ __forceinline__ unsigned key32(float f) {
    unsigned u = __float_as_uint(f);
    return (u & 0x80000000u) ? ~u : (u | 0x80000000u);  // monotonic: larger float -> larger key
}

// ---------------------------------------------------------------------------
// Kernel 1: single-CTA histogram top-k -> mask + compact index list
// grid = 1, block = 1024
// ---------------------------------------------------------------------------
__global__ void __launch_bounds__(1024, 1)
k_topk(const float* __restrict__ logits, float* __restrict__ mask_out) {
    __shared__ unsigned skey[IN_DIM];
    __shared__ int hist[NBIN];
    __shared__ int groupsum[128];
    __shared__ int s_T, s_m, s_ncand;
    __shared__ int      cand_idx[MAXCAND];
    __shared__ unsigned cand_key[MAXCAND];
    __shared__ unsigned char sel[IN_DIM];

    const int tid = threadIdx.x;

    for (int i = tid; i < NBIN; i += 1024) hist[i] = 0;
    if (tid == 0) s_ncand = 0;
    __syncthreads();

    for (int i = tid; i < IN_DIM; i += 1024) {
        unsigned u = key32(logits[i]);
        skey[i] = u;
        atomicAdd(&hist[u >> 20], 1);
    }
    __syncthreads();

    if (tid < 128) {
        int s = 0;
#pragma unroll
        for (int j = 0; j < 32; j++) s += hist[tid * 32 + j];
        groupsum[tid] = s;
    }
    __syncthreads();
    if (tid == 0) {
        int acc = 0, g = 127;
        for (; g > 0; g--) { if (acc + groupsum[g] >= TOPK) break; acc += groupsum[g]; }
        int b = g * 32 + 31;
        for (; b > g * 32; b--) { if (acc + hist[b] >= TOPK) break; acc += hist[b]; }
        s_T = b;
        s_m = TOPK - acc;
    }
    __syncthreads();
    const int T = s_T, m = s_m;

    for (int i = tid; i < IN_DIM; i += 1024) {
        const int b = (int)(skey[i] >> 20);
        sel[i] = (b > T) ? 1 : 0;
        if (b == T) {
            int c = atomicAdd(&s_ncand, 1);
            if (c < MAXCAND) { cand_idx[c] = i; cand_key[c] = skey[i]; }
        }
    }
    __syncthreads();

    const int nc = min(s_ncand, MAXCAND);
    for (int ci = tid; ci < nc; ci += 1024) {
        const unsigned ki = cand_key[ci];
        const int      ii = cand_idx[ci];
        int rank = 0;
        for (int cj = 0; cj < nc; cj++) {
            const unsigned kj = cand_key[cj];
            rank += (kj > ki || (kj == ki && cand_idx[cj] < ii)) ? 1 : 0;
        }
        if (rank < m) sel[ii] = 1;
    }
    __syncthreads();

    if (mask_out)
        for (int i = tid; i < IN_DIM; i += 1024)
            mask_out[i] = sel[i] ? 1.0f : 0.0f;

    if (tid < 32) {
        int base = 0;
        for (int c0 = 0; c0 < IN_DIM; c0 += 32) {
            const int i = c0 + tid;
            const bool s = (i < IN_DIM) && sel[i];
            const unsigned b = __ballot_sync(0xffffffffu, s);
            if (s) g_topk_idx[base + __popc(b & ((1u << tid) - 1u))] = i;
            base += __popc(b);
        }
    }
}

// ---------------------------------------------------------------------------
// Kernel 2: fused gather + MLP. FOUR threads per row, split over K:
//   quarter q handles k = q, q+4, ..., q+48 (13 gathers, 13x32 partial FMA);
//   partials reduced across the quad via shfl_xor(1),shfl_xor(2);
//   layer 2 redundant per quad; layer 3 split 8/8/8/6 across the quad.
// grid = 256, block = 256 (64 rows per CTA)
// ---------------------------------------------------------------------------
__global__ void __launch_bounds__(256, 2)
k_mlp(const float* __restrict__ x,
      const float* __restrict__ W1, const float* __restrict__ b1,
      const float* __restrict__ W2, const float* __restrict__ b2,
      const float* __restrict__ W3, const float* __restrict__ b3,
      float* __restrict__ out) {
    __shared__ int   sidx[TOPK_PAD];
    __shared__ float sW1[TOPK_PAD][H1P];   // zero-padded rows 50,51
    __shared__ float sW2[H1][H2];
    __shared__ float sW3[H2][OUT_DIM];
    __shared__ float sb1[H1], sb2[H2], sb3[OUT_DIM];

    const int tid = threadIdx.x;
    if (tid < TOPK_PAD) sidx[tid] = (tid < TOPK) ? g_topk_idx[tid] : 0;
    if (tid < H1)      sb1[tid] = b1[tid];
    if (tid < H2)      sb2[tid] = b2[tid];
    if (tid < OUT_DIM) sb3[tid] = b3[tid];
    __syncthreads();   // sidx ready before W1 gather

    for (int t = tid; t < TOPK_PAD * H1; t += blockDim.x) {
        const int k = t >> 5, j = t & 31;
        sW1[k][j] = (k < TOPK) ? W1[(long)sidx[k] * H1 + j] : 0.0f;
    }
    for (int t = tid; t < H1 * H2; t += blockDim.x)
        sW2[t / H2][t % H2] = W2[t];
    for (int t = tid; t < H2 * OUT_DIM; t += blockDim.x)
        sW3[t / OUT_DIM][t % OUT_DIM] = W3[t];
    __syncthreads();

    const int row = blockIdx.x * 64 + (tid >> 2);
    const int q   = tid & 3;
    if (row >= BATCH) return;
    const float* __restrict__ xr = x + (long)row * IN_DIM;

    // gather this quarter's 13 inputs first (MLP=13 per thread, 52 per quad)
    float xv[13];
#pragma unroll
    for (int i = 0; i < 13; i++)
        xv[i] = __ldg(xr + sidx[q + 4 * i]);

    // partial layer-1 accumulation over this quarter's k
    float p[H1];
#pragma unroll
    for (int j = 0; j < H1; j++) p[j] = 0.0f;
#pragma unroll
    for (int i = 0; i < 13; i++) {
        const float v = xv[i];
        const int   k = q + 4 * i;
#pragma unroll
        for (int j = 0; j < H1; j++)
            p[j] = fmaf(v, sW1[k][j], p[j]);
    }

    // quad reduction -> full a1, bias, relu (all 4 lanes get the sum)
    float a1[H1];
#pragma unroll
    for (int j = 0; j < H1; j++) {
        float s = p[j];
        s += __shfl_xor_sync(0xffffffffu, s, 1);
        s += __shfl_xor_sync(0xffffffffu, s, 2);
        a1[j] = fmaxf(s + sb1[j], 0.0f);
    }

    // layer 2 (redundant per quad, small)
    float a2[H2];
#pragma unroll
    for (int j = 0; j < H2; j++) a2[j] = sb2[j];
#pragma unroll
    for (int i = 0; i < H1; i++) {
        const float v = a1[i];
#pragma unroll
        for (int j = 0; j < H2; j++)
            a2[j] = fmaf(v, sW2[i][j], a2[j]);
    }
#pragma unroll
    for (int j = 0; j < H2; j++) a2[j] = fmaxf(a2[j], 0.0f);

    // layer 3: quarter q writes columns [8q, 8q+8) (q=3 -> 6 cols)
    float* __restrict__ orow = out + (long)row * OUT_DIM;
    const int j0 = q * 8;
#pragma unroll
    for (int jj = 0; jj < 8; jj++) {
        const int j = j0 + jj;
        if (j < OUT_DIM) {
            float s = sb3[j];
#pragma unroll
            for (int i = 0; i < H2; i++)
                s = fmaf(a2[i], sW3[i][j], s);
            orow[j] = s;
        }
    }
}

// ---------------------------------------------------------------------------
extern "C" void kernel_launch(void* const* d_in, const int* in_sizes, int n_in,
                              void* d_out, int out_size) {
    const float* x      = (const float*)d_in[0];
    const float* logits = (const float*)d_in[1];
    const float* W1     = (const float*)d_in[2];
    const float* b1     = (const float*)d_in[3];
    const float* W2     = (const float*)d_in[4];
    const float* b2     = (const float*)d_in[5];
    const float* W3     = (const float*)d_in[6];
    const float* b3     = (const float*)d_in[7];

    float* out  = (float*)d_out;
    float* mask = nullptr;
    if (out_size >= BATCH * OUT_DIM + IN_DIM)
        mask = out + (long)BATCH * OUT_DIM;   // tuple order: (out, mask)

    k_topk<<<1, 1024>>>(logits, mask);
    k_mlp <<<256, 256>>>(x, W1, b1, W2, b2, W3, b3, out);
}